// round 3
// baseline (speedup 1.0000x reference)
#include <cuda_runtime.h>
#include <cstdint>

#define B  32
#define D  768
#define H  3072
#define T  8
#define MH 192

typedef unsigned long long ull;

// ---------------- scratch (device globals) ----------------------------------
__device__ float g_m  [B*D];
__device__ float g_f0 [B*D];
__device__ float g_Ap [B*T*D];
__device__ float g_z  [B*H];
__device__ float g_f  [B*H];
__device__ float g_Z1 [B*T*H];
__device__ float g_base[B*D];
__device__ float g_F2 [B*T*D];
__device__ float g_coef[B*T*6];
__device__ float g_df0[B*D];
__device__ float g_dzp[B*H];
__device__ float g_df [B*H];

// ---------------- packed f32x2 helpers --------------------------------------
__device__ __forceinline__ void ffma2(ull &d, ull a, ull b) {
    asm("fma.rn.f32x2 %0, %1, %2, %0;" : "+l"(d) : "l"(a), "l"(b));
}
__device__ __forceinline__ ull bcast2(float w) {
    ull r; asm("mov.b64 %0, {%1, %1};" : "=l"(r) : "f"(w)); return r;
}
__device__ __forceinline__ void unpack2(ull v, float &lo, float &hi) {
    asm("mov.b64 {%0, %1}, %2;" : "=f"(lo), "=f"(hi) : "l"(v));
}
__device__ __forceinline__ void red4(float* p, float4 f) {
    asm volatile("red.global.add.v4.f32 [%0], {%1,%2,%3,%4};"
                 :: "l"(p), "f"(f.x), "f"(f.y), "f"(f.z), "f"(f.w) : "memory");
}
__device__ __forceinline__ void cpasync16(unsigned dstp, const float* src) {
    asm volatile("cp.async.ca.shared.global [%0], [%1], 16;" :: "r"(dstp), "l"(src));
}

// ---------------- K1: patch mean ---------------------------------------------
__global__ void patch_mean_kernel(const float* __restrict__ x) {
    int bc = blockIdx.x;            // 0..95
    int b = bc / 3, c = bc % 3;
    int tid = threadIdx.x;          // 256
    int dy = tid >> 4, dx = tid & 15;
    const float* base = x + (((size_t)b * 3 + c) * 224 + dy) * 224 + dx;
    float s = 0.f;
    #pragma unroll
    for (int py = 0; py < 14; py++) {
        const float* r = base + py * 16 * 224;
        #pragma unroll
        for (int px = 0; px < 14; px++) s += r[px * 16];
    }
    g_m[b * D + c * 256 + dy * 16 + dx] = s * (1.0f / 196.0f);
}

// ---------------- init: bias preload + zeros for atomic accumulation --------
__global__ void init_kernel(const float* __restrict__ bp,
                            const float* __restrict__ b1,
                            const float* __restrict__ b2) {
    int i = blockIdx.x * 256 + threadIdx.x;      // grid 384 covers B*H
    if (i < B * D) { g_f0[i] = bp[i % D]; g_base[i] = b2[i % D]; }
    if (i < B * H) g_z[i] = b1[i % H];
    for (int j = i; j < B * T * D; j += gridDim.x * 256) { g_Ap[j] = 0.f; g_F2[j] = 0.f; }
    for (int j = i; j < B * T * H; j += gridDim.x * 256) g_Z1[j] = 0.f;
}

__global__ void relu_kernel() {
    int i = blockIdx.x * 256 + threadIdx.x;
    if (i < B * H) g_f[i] = fmaxf(g_z[i], 0.f);
}
__global__ void mask_kernel() {
    int i = blockIdx.x * 256 + threadIdx.x;
    if (i < B * H) g_df[i] = (g_z[i] > 0.f) ? g_dzp[i] : 0.f;
}

// ---------------- skinny GEMM v3: cp.async pipelined weights ----------------
// Block tile: 128 cols x 32 rows, k-split over grid.y. 8 warps:
//   cg = w&3 (32 cols), rh = w>>2 (16 rows); lane owns 1 col, 16 rows.
// acc: 8 packed row-pairs. Flush via smem repack + red.global.add.v4.
// MODE: 0:g_f0/g_Ap  1:g_z/g_Z1  2:g_base/g_F2  3:g_dzp(A=g_df0)  4:dst(A=g_df)
template<int KTOT, int NC, int MODE>
__global__ void __launch_bounds__(256, 3) gemm3(
    const float* __restrict__ W0,
    const float* __restrict__ Wd,
    float* __restrict__ dst)
{
    __shared__ __align__(16) float sW[3 * 16 * 128];   // 24KB, 3 stages
    __shared__ __align__(16) float sA[2 * 16 * 32];    // 4KB, 2 buffers

    const int tid  = threadIdx.x;
    const int w    = tid >> 5;
    const int lane = tid & 31;
    const int cg   = w & 3;
    const int rh   = w >> 2;

    const float* A;
    if      (MODE == 0) A = g_m;
    else if (MODE == 1) A = g_f0;
    else if (MODE == 2) A = g_f;
    else if (MODE == 3) A = g_df0;
    else                A = g_df;

    const int n0 = blockIdx.x * 128;
    const int gt = n0 / NC;
    const int c0 = n0 % NC;
    const float* wbase = (gt == 0 ? W0 : Wd + (size_t)(gt - 1) * KTOT * NC) + c0;

    const int KC    = KTOT / gridDim.y;
    const int kbeg  = blockIdx.y * KC;
    const int tiles = KC >> 4;

    // cp.async staging indices (2 x 16B per thread per tile)
    const int r0s = tid >> 4;                     // rows 0..15 (i=0)
    const int s0s = tid & 15;                     // hmm: use idx mapping below

    ull acc[8];
    #pragma unroll
    for (int i = 0; i < 8; i++) acc[i] = 0ULL;

    // ---- W issue helper (macro-style, 2 ops/thread) ----
    #define ISSUE_W(t)                                                          \
    {                                                                           \
        const int st_ = (t) % 3;                                                \
        _Pragma("unroll")                                                       \
        for (int i_ = 0; i_ < 2; i_++) {                                        \
            int idx_ = i_ * 256 + tid;                                          \
            int row_ = idx_ >> 5, seg_ = idx_ & 31;                             \
            const float* src_ = wbase + (size_t)(kbeg + (t) * 16 + row_) * NC + seg_ * 4; \
            unsigned dp_ = (unsigned)__cvta_generic_to_shared(                  \
                               &sW[st_ * 2048 + row_ * 128 + seg_ * 4]);        \
            cpasync16(dp_, src_);                                               \
        }                                                                       \
        asm volatile("cp.async.commit_group;");                                 \
    }
    (void)r0s; (void)s0s;

    // A prefetch: thread loads 2 consecutive k for one row
    const int arow = lane;
    const int kk   = (tid >> 5) * 2;
    const float* aptr = A + (size_t)arow * KTOT + kbeg + kk;
    float2 av = *(const float2*)aptr;

    // prologue: 2 stages in flight
    ISSUE_W(0);
    if (tiles > 1) { ISSUE_W(1); } else { asm volatile("cp.async.commit_group;"); }

    for (int t = 0; t < tiles; t++) {
        asm volatile("cp.async.wait_group 1;");
        __syncthreads();
        // stage A tile t (transposed [k][row])
        float* sAb = &sA[(t & 1) * 512];
        sAb[kk * 32 + arow]       = av.x;
        sAb[(kk + 1) * 32 + arow] = av.y;
        if (t + 1 < tiles) av = *(const float2*)(aptr + (t + 1) * 16);
        if (t + 2 < tiles) { ISSUE_W(t + 2); }
        else               { asm volatile("cp.async.commit_group;"); }
        __syncthreads();

        const float* sWb = &sW[(t % 3) * 2048 + cg * 32 + lane];
        const float* sAr = sAb + rh * 16;
        #pragma unroll
        for (int k = 0; k < 16; k++) {
            ull w2 = bcast2(sWb[k * 128]);
            const ulonglong2* ap = (const ulonglong2*)(sAr + k * 32);
            ulonglong2 q0 = ap[0], q1 = ap[1], q2 = ap[2], q3 = ap[3];
            ffma2(acc[0], q0.x, w2); ffma2(acc[1], q0.y, w2);
            ffma2(acc[2], q1.x, w2); ffma2(acc[3], q1.y, w2);
            ffma2(acc[4], q2.x, w2); ffma2(acc[5], q2.y, w2);
            ffma2(acc[6], q3.x, w2); ffma2(acc[7], q3.y, w2);
        }
    }
    #undef ISSUE_W

    // ---- repack through smem, flush with red.v4 ----
    __syncthreads();
    float* sF = sW;                        // 32x128 floats = 16KB (stages 0-1)
    #pragma unroll
    for (int p = 0; p < 8; p++) {
        float lo, hi; unpack2(acc[p], lo, hi);
        int r = rh * 16 + 2 * p;
        sF[r * 128 + cg * 32 + lane]       = lo;
        sF[(r + 1) * 128 + cg * 32 + lane] = hi;
    }
    __syncthreads();
    #pragma unroll
    for (int i = 0; i < 4; i++) {
        int v = i * 256 + tid;
        int row = v >> 5, colq = v & 31;
        float4 f = ((const float4*)sF)[v];
        const int c = c0 + colq * 4;
        float* p;
        if constexpr (MODE == 0)
            p = (gt == 0) ? &g_f0[row * D + c]
                          : &g_Ap[((size_t)row * T + gt - 1) * D + c];
        else if constexpr (MODE == 1)
            p = (gt == 0) ? &g_z[row * H + c]
                          : &g_Z1[((size_t)row * T + gt - 1) * H + c];
        else if constexpr (MODE == 2)
            p = (gt == 0) ? &g_base[row * D + c]
                          : &g_F2[((size_t)row * T + gt - 1) * D + c];
        else if constexpr (MODE == 3)
            p = &g_dzp[row * H + c];
        else
            p = &dst[row * D + c];
        red4(p, f);
    }
}

// ---------------- K5: metanet -------------------------------------------------
__global__ void meta_kernel(const float* __restrict__ mW1, const float* __restrict__ mb1,
                            const float* __restrict__ mW2, const float* __restrict__ mb2)
{
    __shared__ float sb[D];
    __shared__ float sg[MH];
    const int b = blockIdx.x;
    const int tid = threadIdx.x;   // 192
    for (int i = tid; i < D; i += MH) sb[i] = g_base[b * D + i];
    __syncthreads();
    float h = mb1[tid];
    #pragma unroll 8
    for (int k = 0; k < D; k++) h = fmaf(sb[k], mW1[k * MH + tid], h);
    sg[tid] = fmaxf(h, 0.f);
    __syncthreads();
    if (tid < T * 6) {
        float cc = mb2[tid];
        #pragma unroll 8
        for (int k = 0; k < MH; k++) cc = fmaf(sg[k], mW2[k * (T * 6) + tid], cc);
        g_coef[b * (T * 6) + tid] = cc;
    }
}

// ---------------- K6: coefficient contraction + output init ------------------
__global__ void combine_kernel(const float* __restrict__ dbp,
                               const float* __restrict__ db1,
                               const float* __restrict__ db2,
                               float* __restrict__ dst)
{
    __shared__ float sc[T * 6];
    const int b = blockIdx.x;
    const int tid = threadIdx.x;
    if (tid < T * 6) sc[tid] = g_coef[b * (T * 6) + tid];
    __syncthreads();
    const int n = blockIdx.y * 256 + tid;
    if (n < D) {
        float s = 0.f;
        #pragma unroll
        for (int t = 0; t < T; t++)
            s += sc[t * 6 + 0] * g_Ap[((size_t)b * T + t) * D + n]
               + sc[t * 6 + 1] * dbp[t * D + n];
        g_df0[b * D + n] = s;
    } else if (n < D + H) {
        const int j = n - D;
        float s = 0.f;
        #pragma unroll
        for (int t = 0; t < T; t++)
            s += sc[t * 6 + 2] * g_Z1[((size_t)b * T + t) * H + j]
               + sc[t * 6 + 3] * db1[t * H + j];
        g_dzp[b * H + j] = s;
    } else {
        const int j = n - D - H;
        float s = g_base[b * D + j];
        #pragma unroll
        for (int t = 0; t < T; t++)
            s += sc[t * 6 + 4] * g_F2[((size_t)b * T + t) * D + j]
               + sc[t * 6 + 5] * db2[t * D + j];
        dst[b * D + j] = s;
    }
}

// ---------------- launch ------------------------------------------------------
extern "C" void kernel_launch(void* const* d_in, const int* in_sizes, int n_in,
                              void* d_out, int out_size)
{
    const float* x   = (const float*)d_in[0];
    const float* Wp  = (const float*)d_in[1];
    const float* bp  = (const float*)d_in[2];
    const float* W1  = (const float*)d_in[3];
    const float* b1  = (const float*)d_in[4];
    const float* W2  = (const float*)d_in[5];
    const float* b2  = (const float*)d_in[6];
    const float* dWp = (const float*)d_in[7];
    const float* dbp = (const float*)d_in[8];
    const float* dW1 = (const float*)d_in[9];
    const float* db1 = (const float*)d_in[10];
    const float* dW2 = (const float*)d_in[11];
    const float* db2 = (const float*)d_in[12];
    const float* mW1 = (const float*)d_in[13];
    const float* mb1 = (const float*)d_in[14];
    const float* mW2 = (const float*)d_in[15];
    const float* mb2 = (const float*)d_in[16];
    float* out = (float*)d_out;

    patch_mean_kernel<<<96, 256>>>(x);
    init_kernel<<<384, 256>>>(bp, b1, b2);
    // K2: f0/Ap   N=9*768 -> 54 nblk,  Y=8  (KC=96,  6 tiles)  432 blocks
    gemm3<768, 768, 0><<<dim3(54, 8), 256>>>(Wp, dWp, nullptr);
    // K3: z/Z1    N=9*3072 -> 216 nblk, Y=2 (KC=384, 24 tiles) 432 blocks
    gemm3<768, 3072, 1><<<dim3(216, 2), 256>>>(W1, dW1, nullptr);
    relu_kernel<<<384, 256>>>();
    // K4: base/F2 N=9*768 -> 54 nblk, Y=8  (KC=384, 24 tiles)  432 blocks
    gemm3<3072, 768, 2><<<dim3(54, 8), 256>>>(W2, dW2, nullptr);
    meta_kernel<<<B, MH>>>(mW1, mb1, mW2, mb2);
    combine_kernel<<<dim3(B, 18), 256>>>(dbp, db1, db2, out);
    // K7: dzp += df0@W1  N=3072 -> 24 nblk, Y=16 (KC=48, 3 tiles) 384 blocks
    gemm3<768, 3072, 3><<<dim3(24, 16), 256>>>(W1, nullptr, nullptr);
    mask_kernel<<<384, 256>>>();
    // K8: out += df@W2   N=768 -> 6 nblk,  Y=48 (KC=64, 4 tiles) 288 blocks
    gemm3<3072, 768, 4><<<dim3(6, 48), 256>>>(W2, nullptr, out);
}

// round 4
// speedup vs baseline: 1.1878x; 1.1878x over previous
#include <cuda_runtime.h>
#include <cstdint>

#define B  32
#define D  768
#define H  3072
#define T  8
#define MH 192

typedef unsigned long long ull;

// ---------------- scratch (device globals) ----------------------------------
__device__ float g_m  [B*D];
__device__ float g_f0 [B*D];
__device__ float g_Ap [B*T*D];
__device__ float g_z  [B*H];
__device__ float g_f  [B*H];
__device__ float g_Z1 [B*T*H];
__device__ float g_base[B*D];
__device__ float g_F2 [B*T*D];
__device__ float g_coef[B*T*6];
__device__ float g_df0[B*D];
__device__ float g_dzp[B*H];
__device__ float g_df [B*H];

// ---------------- packed f32x2 helpers --------------------------------------
__device__ __forceinline__ void ffma2(ull &d, ull a, ull b) {
    asm("fma.rn.f32x2 %0, %1, %2, %0;" : "+l"(d) : "l"(a), "l"(b));
}
__device__ __forceinline__ ull bcast2(float w) {
    ull r; asm("mov.b64 %0, {%1, %1};" : "=l"(r) : "f"(w)); return r;
}
__device__ __forceinline__ void unpack2(ull v, float &lo, float &hi) {
    asm("mov.b64 {%0, %1}, %2;" : "=f"(lo), "=f"(hi) : "l"(v));
}
__device__ __forceinline__ void red4(float* p, float4 f) {
    asm volatile("red.global.add.v4.f32 [%0], {%1,%2,%3,%4};"
                 :: "l"(p), "f"(f.x), "f"(f.y), "f"(f.z), "f"(f.w) : "memory");
}
__device__ __forceinline__ void cpasync16(unsigned dstp, const float* src) {
    asm volatile("cp.async.ca.shared.global [%0], [%1], 16;" :: "r"(dstp), "l"(src));
}

// ---------------- K1: patch mean ---------------------------------------------
__global__ void patch_mean_kernel(const float* __restrict__ x) {
    int bc = blockIdx.x;            // 0..95
    int b = bc / 3, c = bc % 3;
    int tid = threadIdx.x;          // 256
    int dy = tid >> 4, dx = tid & 15;
    const float* base = x + (((size_t)b * 3 + c) * 224 + dy) * 224 + dx;
    float s = 0.f;
    #pragma unroll
    for (int py = 0; py < 14; py++) {
        const float* r = base + py * 16 * 224;
        #pragma unroll
        for (int px = 0; px < 14; px++) s += r[px * 16];
    }
    g_m[b * D + c * 256 + dy * 16 + dx] = s * (1.0f / 196.0f);
}

// ---------------- init: bias preload + zeros ---------------------------------
__global__ void init_kernel(const float* __restrict__ bp,
                            const float* __restrict__ b1,
                            const float* __restrict__ b2) {
    int i = blockIdx.x * 256 + threadIdx.x;
    if (i < B * D) { g_f0[i] = bp[i % D]; g_base[i] = b2[i % D]; }
    if (i < B * H) g_z[i] = b1[i % H];
    for (int j = i; j < B * T * D; j += gridDim.x * 256) { g_Ap[j] = 0.f; g_F2[j] = 0.f; }
    for (int j = i; j < B * T * H; j += gridDim.x * 256) g_Z1[j] = 0.f;
}

__global__ void relu_kernel() {
    int i = blockIdx.x * 256 + threadIdx.x;
    if (i < B * H) g_f[i] = fmaxf(g_z[i], 0.f);
}
__global__ void mask_kernel() {
    int i = blockIdx.x * 256 + threadIdx.x;
    if (i < B * H) g_df[i] = (g_z[i] > 0.f) ? g_dzp[i] : 0.f;
}

// ---------------- skinny GEMM v4 ---------------------------------------------
// Tile: 128 cols x 32 rows. 8 warps = 4 ksegs (4k each of a 16k tile) x 2 row
// halves. Lane owns 4 consecutive cols. f32x2 packed over COLUMN pairs:
// W read as ulonglong2 from cp.async-staged smem tile; A scalar broadcast.
// 32 ffma2 per k per warp vs 8 L1 wavefronts -> fma-bound.
// MODE: 0:g_f0/g_Ap  1:g_z/g_Z1  2:g_base/g_F2  3:g_dzp(A=g_df0)  4:dst(A=g_df)
template<int KTOT, int NC, int MODE>
__global__ void __launch_bounds__(256, 2) gemm4(
    const float* __restrict__ W0,
    const float* __restrict__ Wd,
    float* __restrict__ dst)
{
    __shared__ __align__(16) float sW[3 * 2048];   // 24KB, 3 stages of 16k x 128
    __shared__ __align__(16) float sA[2 * 512];    // 4KB, 2 buffers of 16k x 32

    const int tid  = threadIdx.x;
    const int w    = tid >> 5;
    const int lane = tid & 31;
    const int ks   = w >> 1;      // k sub-segment within 16k tile
    const int bh   = w & 1;       // row half

    const float* A;
    if      (MODE == 0) A = g_m;
    else if (MODE == 1) A = g_f0;
    else if (MODE == 2) A = g_f;
    else if (MODE == 3) A = g_df0;
    else                A = g_df;

    const int n0 = blockIdx.x * 128;
    const int gt = n0 / NC;
    const int c0 = n0 % NC;
    const float* wbase = (gt == 0 ? W0 : Wd + (size_t)(gt - 1) * KTOT * NC) + c0;

    const int KC    = KTOT / gridDim.y;
    const int kbeg  = blockIdx.y * KC;
    const int tiles = KC >> 4;

    ull acc[32];
    #pragma unroll
    for (int i = 0; i < 32; i++) acc[i] = 0ULL;

    #define ISSUE_W(t)                                                          \
    {                                                                           \
        const int st_ = (t) % 3;                                                \
        _Pragma("unroll")                                                       \
        for (int i_ = 0; i_ < 2; i_++) {                                        \
            int idx_ = i_ * 256 + tid;                                          \
            int row_ = idx_ >> 5, seg_ = idx_ & 31;                             \
            const float* src_ = wbase + (size_t)(kbeg + (t) * 16 + row_) * NC + seg_ * 4; \
            unsigned dp_ = (unsigned)__cvta_generic_to_shared(                  \
                               &sW[st_ * 2048 + row_ * 128 + seg_ * 4]);        \
            cpasync16(dp_, src_);                                               \
        }                                                                       \
        asm volatile("cp.async.commit_group;");                                 \
    }

    // A prefetch: thread stages 2 consecutive k of one row
    const int arow = lane;
    const int kk2  = (tid >> 5) * 2;
    const float* aptr = A + (size_t)arow * KTOT + kbeg + kk2;
    float2 av = *(const float2*)aptr;

    ISSUE_W(0);
    if (tiles > 1) { ISSUE_W(1); } else { asm volatile("cp.async.commit_group;"); }

    for (int t = 0; t < tiles; t++) {
        asm volatile("cp.async.wait_group 1;");
        __syncthreads();
        float* sAb = &sA[(t & 1) * 512];
        sAb[kk2 * 32 + arow]       = av.x;
        sAb[(kk2 + 1) * 32 + arow] = av.y;
        if (t + 1 < tiles) av = *(const float2*)(aptr + (t + 1) * 16);
        if (t + 2 < tiles) { ISSUE_W(t + 2); }
        else               { asm volatile("cp.async.commit_group;"); }
        __syncthreads();

        const float* sWb = &sW[(t % 3) * 2048 + (ks * 4) * 128 + 4 * lane];
        const float* sAr = sAb + (ks * 4) * 32 + bh * 16;
        #pragma unroll
        for (int kk = 0; kk < 4; kk++) {
            ulonglong2 wv = *(const ulonglong2*)(sWb + kk * 128);
            const float4* ap = (const float4*)(sAr + kk * 32);
            float4 a0 = ap[0], a1 = ap[1], a2 = ap[2], a3 = ap[3];
            float fr[16] = {a0.x, a0.y, a0.z, a0.w, a1.x, a1.y, a1.z, a1.w,
                            a2.x, a2.y, a2.z, a2.w, a3.x, a3.y, a3.z, a3.w};
            #pragma unroll
            for (int r = 0; r < 16; r++) {
                ull ab = bcast2(fr[r]);
                ffma2(acc[2 * r],     ab, wv.x);
                ffma2(acc[2 * r + 1], ab, wv.y);
            }
        }
    }
    #undef ISSUE_W

    // ---- kseg reduction in smem (float4-shaped, no transpose) ----
    __syncthreads();
    float* sF = sW;                 // 32 x 128 floats = 16KB
    #pragma unroll
    for (int r = 0; r < 4; r++) {
        if (ks == r) {
            #pragma unroll
            for (int rr = 0; rr < 16; rr++) {
                float4 v;
                unpack2(acc[2 * rr],     v.x, v.y);
                unpack2(acc[2 * rr + 1], v.z, v.w);
                float* p = &sF[(bh * 16 + rr) * 128 + 4 * lane];
                if (r == 0) {
                    *(float4*)p = v;
                } else {
                    float4 o = *(const float4*)p;
                    o.x += v.x; o.y += v.y; o.z += v.z; o.w += v.w;
                    *(float4*)p = o;
                }
            }
        }
        __syncthreads();
    }

    // ---- flush with red.global.add.v4 ----
    #pragma unroll
    for (int i = 0; i < 4; i++) {
        int v = i * 256 + tid;
        int row = v >> 5, colq = v & 31;
        float4 f = ((const float4*)sF)[v];
        const int c = c0 + colq * 4;
        float* p;
        if constexpr (MODE == 0)
            p = (gt == 0) ? &g_f0[row * D + c]
                          : &g_Ap[((size_t)row * T + gt - 1) * D + c];
        else if constexpr (MODE == 1)
            p = (gt == 0) ? &g_z[row * H + c]
                          : &g_Z1[((size_t)row * T + gt - 1) * H + c];
        else if constexpr (MODE == 2)
            p = (gt == 0) ? &g_base[row * D + c]
                          : &g_F2[((size_t)row * T + gt - 1) * D + c];
        else if constexpr (MODE == 3)
            p = &g_dzp[row * H + c];
        else
            p = &dst[row * D + c];
        red4(p, f);
    }
}

// ---------------- K5: metanet -------------------------------------------------
__global__ void meta_kernel(const float* __restrict__ mW1, const float* __restrict__ mb1,
                            const float* __restrict__ mW2, const float* __restrict__ mb2)
{
    __shared__ float sb[D];
    __shared__ float sg[MH];
    const int b = blockIdx.x;
    const int tid = threadIdx.x;   // 192
    for (int i = tid; i < D; i += MH) sb[i] = g_base[b * D + i];
    __syncthreads();
    float h = mb1[tid];
    #pragma unroll 8
    for (int k = 0; k < D; k++) h = fmaf(sb[k], mW1[k * MH + tid], h);
    sg[tid] = fmaxf(h, 0.f);
    __syncthreads();
    if (tid < T * 6) {
        float cc = mb2[tid];
        #pragma unroll 8
        for (int k = 0; k < MH; k++) cc = fmaf(sg[k], mW2[k * (T * 6) + tid], cc);
        g_coef[b * (T * 6) + tid] = cc;
    }
}

// ---------------- K6: coefficient contraction + output init ------------------
__global__ void combine_kernel(const float* __restrict__ dbp,
                               const float* __restrict__ db1,
                               const float* __restrict__ db2,
                               float* __restrict__ dst)
{
    __shared__ float sc[T * 6];
    const int b = blockIdx.x;
    const int tid = threadIdx.x;
    if (tid < T * 6) sc[tid] = g_coef[b * (T * 6) + tid];
    __syncthreads();
    const int n = blockIdx.y * 256 + tid;
    if (n < D) {
        float s = 0.f;
        #pragma unroll
        for (int t = 0; t < T; t++)
            s += sc[t * 6 + 0] * g_Ap[((size_t)b * T + t) * D + n]
               + sc[t * 6 + 1] * dbp[t * D + n];
        g_df0[b * D + n] = s;
    } else if (n < D + H) {
        const int j = n - D;
        float s = 0.f;
        #pragma unroll
        for (int t = 0; t < T; t++)
            s += sc[t * 6 + 2] * g_Z1[((size_t)b * T + t) * H + j]
               + sc[t * 6 + 3] * db1[t * H + j];
        g_dzp[b * H + j] = s;
    } else {
        const int j = n - D - H;
        float s = g_base[b * D + j];
        #pragma unroll
        for (int t = 0; t < T; t++)
            s += sc[t * 6 + 4] * g_F2[((size_t)b * T + t) * D + j]
               + sc[t * 6 + 5] * db2[t * D + j];
        dst[b * D + j] = s;
    }
}

// ---------------- launch ------------------------------------------------------
extern "C" void kernel_launch(void* const* d_in, const int* in_sizes, int n_in,
                              void* d_out, int out_size)
{
    const float* x   = (const float*)d_in[0];
    const float* Wp  = (const float*)d_in[1];
    const float* bp  = (const float*)d_in[2];
    const float* W1  = (const float*)d_in[3];
    const float* b1  = (const float*)d_in[4];
    const float* W2  = (const float*)d_in[5];
    const float* b2  = (const float*)d_in[6];
    const float* dWp = (const float*)d_in[7];
    const float* dbp = (const float*)d_in[8];
    const float* dW1 = (const float*)d_in[9];
    const float* db1 = (const float*)d_in[10];
    const float* dW2 = (const float*)d_in[11];
    const float* db2 = (const float*)d_in[12];
    const float* mW1 = (const float*)d_in[13];
    const float* mb1 = (const float*)d_in[14];
    const float* mW2 = (const float*)d_in[15];
    const float* mb2 = (const float*)d_in[16];
    float* out = (float*)d_out;

    patch_mean_kernel<<<96, 256>>>(x);
    init_kernel<<<384, 256>>>(bp, b1, b2);
    // K2: f0/Ap   N=9*768  -> 54 nblk, Y=12 (KC=64,  4 tiles)  648 blocks
    gemm4<768, 768, 0><<<dim3(54, 12), 256>>>(Wp, dWp, nullptr);
    // K3: z/Z1    N=9*3072 -> 216 nblk, Y=4 (KC=192, 12 tiles) 864 blocks
    gemm4<768, 3072, 1><<<dim3(216, 4), 256>>>(W1, dW1, nullptr);
    relu_kernel<<<384, 256>>>();
    // K4: base/F2 N=9*768  -> 54 nblk, Y=16 (KC=192, 12 tiles) 864 blocks
    gemm4<3072, 768, 2><<<dim3(54, 16), 256>>>(W2, dW2, nullptr);
    meta_kernel<<<B, MH>>>(mW1, mb1, mW2, mb2);
    combine_kernel<<<dim3(B, 18), 256>>>(dbp, db1, db2, out);
    // K7: dzp += df0@W1  N=3072 -> 24 nblk, Y=12 (KC=64, 4 tiles) 288 blocks
    gemm4<768, 3072, 3><<<dim3(24, 12), 256>>>(W1, nullptr, nullptr);
    mask_kernel<<<384, 256>>>();
    // K8: out += df@W2   N=768  -> 6 nblk, Y=48 (KC=64, 4 tiles) 288 blocks
    gemm4<3072, 768, 4><<<dim3(6, 48), 256>>>(W2, nullptr, out);
}

// round 5
// speedup vs baseline: 1.2691x; 1.0685x over previous
#include <cuda_runtime.h>
#include <cstdint>

#define B  32
#define D  768
#define H  3072
#define T  8
#define MH 192

typedef unsigned long long ull;

// ---------------- scratch (device globals) ----------------------------------
__device__ float g_m  [B*D];
__device__ float g_f0 [B*D];
__device__ float g_Ap [B*T*D];
__device__ float g_z  [B*H];
__device__ float g_f  [B*H];
__device__ float g_Z1 [B*T*H];
__device__ float g_base[B*D];
__device__ float g_F2 [B*T*D];
__device__ float g_coef[B*T*6];
__device__ float g_df0[B*D];
__device__ float g_dzp[B*H];
__device__ float g_df [B*H];

// ---------------- packed f32x2 helpers --------------------------------------
__device__ __forceinline__ void ffma2(ull &d, ull a, ull b) {
    asm("fma.rn.f32x2 %0, %1, %2, %0;" : "+l"(d) : "l"(a), "l"(b));
}
__device__ __forceinline__ ull bcast2(float w) {
    ull r; asm("mov.b64 %0, {%1, %1};" : "=l"(r) : "f"(w)); return r;
}
__device__ __forceinline__ void unpack2(ull v, float &lo, float &hi) {
    asm("mov.b64 {%0, %1}, %2;" : "=f"(lo), "=f"(hi) : "l"(v));
}
__device__ __forceinline__ void red4(float* p, float4 f) {
    asm volatile("red.global.add.v4.f32 [%0], {%1,%2,%3,%4};"
                 :: "l"(p), "f"(f.x), "f"(f.y), "f"(f.z), "f"(f.w) : "memory");
}
__device__ __forceinline__ void cpasync16(unsigned dstp, const float* src) {
    asm volatile("cp.async.ca.shared.global [%0], [%1], 16;" :: "r"(dstp), "l"(src));
}

// ---------------- K1: patch mean ---------------------------------------------
__global__ void patch_mean_kernel(const float* __restrict__ x) {
    int bc = blockIdx.x;            // 0..95
    int b = bc / 3, c = bc % 3;
    int tid = threadIdx.x;          // 256
    int dy = tid >> 4, dx = tid & 15;
    const float* base = x + (((size_t)b * 3 + c) * 224 + dy) * 224 + dx;
    float s = 0.f;
    #pragma unroll
    for (int py = 0; py < 14; py++) {
        const float* r = base + py * 16 * 224;
        #pragma unroll
        for (int px = 0; px < 14; px++) s += r[px * 16];
    }
    g_m[b * D + c * 256 + dy * 16 + dx] = s * (1.0f / 196.0f);
}

// ---------------- init: bias preload + zeros ---------------------------------
__global__ void init_kernel(const float* __restrict__ bp,
                            const float* __restrict__ b1,
                            const float* __restrict__ b2) {
    int i = blockIdx.x * 256 + threadIdx.x;
    if (i < B * D) { g_f0[i] = bp[i % D]; g_base[i] = b2[i % D]; }
    if (i < B * H) g_z[i] = b1[i % H];
    for (int j = i; j < B * T * D; j += gridDim.x * 256) { g_Ap[j] = 0.f; g_F2[j] = 0.f; }
    for (int j = i; j < B * T * H; j += gridDim.x * 256) g_Z1[j] = 0.f;
}

__global__ void relu_kernel() {
    int i = blockIdx.x * 256 + threadIdx.x;
    if (i < B * H) g_f[i] = fmaxf(g_z[i], 0.f);
}
__global__ void mask_kernel() {
    int i = blockIdx.x * 256 + threadIdx.x;
    if (i < B * H) g_df[i] = (g_z[i] > 0.f) ? g_dzp[i] : 0.f;
}

// ---------------- skinny GEMM v5 ---------------------------------------------
// Tile 256 cols x 32 rows. 8 warps = 2 col-tiles (ct) x 4 row-quads (rq, 8 rows).
// Lane: 4 consecutive cols, 4 row-pairs packed f32x2 over ROWS.
// Per warp per k: 1 LDS.128 W + 2 broadcast LDS.128 A + 4 bcast + 16 ffma2.
// W: 4-stage cp.async of 8k x 256 tiles. A: double-buffered [k][row] smem.
// One __syncthreads per tile. No in-block k reduction: red.global.add.v4 flush.
// MODE: 0:g_f0/g_Ap  1:g_z/g_Z1  2:g_base/g_F2  3:g_dzp(A=g_df0)  4:dst(A=g_df)
template<int KTOT, int NC, int MODE>
__global__ void __launch_bounds__(256, 3) gemm5(
    const float* __restrict__ W0,
    const float* __restrict__ Wd,
    float* __restrict__ dst)
{
    __shared__ __align__(16) float sW[4 * 2048];   // 32KB: 4 stages of 8k x 256
    __shared__ __align__(16) float sA[2 * 256];    // 2KB: 2 buffers of 8k x 32

    const int tid  = threadIdx.x;
    const int w    = tid >> 5;
    const int lane = tid & 31;
    const int ct   = w & 1;       // col tile (128 cols)
    const int rq   = w >> 1;      // row quad (8 rows)

    const float* A;
    if      (MODE == 0) A = g_m;
    else if (MODE == 1) A = g_f0;
    else if (MODE == 2) A = g_f;
    else if (MODE == 3) A = g_df0;
    else                A = g_df;

    const int n0 = blockIdx.x * 256;
    const int gt = n0 / NC;
    const int c0 = n0 % NC;
    const float* wbase = (gt == 0 ? W0 : Wd + (size_t)(gt - 1) * KTOT * NC) + c0;

    const int KC    = KTOT / gridDim.y;
    const int kbeg  = blockIdx.y * KC;
    const int tiles = KC >> 3;                     // 8 k per tile

    ull acc[16];                                    // [p*4 + c]
    #pragma unroll
    for (int i = 0; i < 16; i++) acc[i] = 0ULL;

    // W issue: 8 rows x 256 cols = 512 x 16B chunks, 2 per thread
    #define ISSUE_W(t)                                                          \
    {                                                                           \
        const int st_ = (t) & 3;                                                \
        _Pragma("unroll")                                                       \
        for (int i_ = 0; i_ < 2; i_++) {                                        \
            int idx_ = i_ * 256 + tid;                                          \
            int row_ = idx_ >> 6, seg_ = idx_ & 63;                             \
            const float* src_ = wbase + (size_t)(kbeg + (t) * 8 + row_) * NC + seg_ * 4; \
            unsigned dp_ = (unsigned)__cvta_generic_to_shared(                  \
                               &sW[st_ * 2048 + row_ * 256 + seg_ * 4]);        \
            cpasync16(dp_, src_);                                               \
        }                                                                       \
        asm volatile("cp.async.commit_group;");                                 \
    }
    #define COMMIT_EMPTY asm volatile("cp.async.commit_group;")

    // A prefetch: thread stages element (k = tid>>5, row = tid&31)
    const int arow = tid & 31, akk = tid >> 5;
    const float* aptr = A + (size_t)arow * KTOT + kbeg + akk;
    float av = *aptr;

    ISSUE_W(0);
    if (tiles > 1) { ISSUE_W(1); } else { COMMIT_EMPTY; }
    if (tiles > 2) { ISSUE_W(2); } else { COMMIT_EMPTY; }

    for (int t = 0; t < tiles; t++) {
        asm volatile("cp.async.wait_group 2;");
        // stage A tile t: [k][row], conflict-free (lane = row)
        sA[(t & 1) * 256 + akk * 32 + arow] = av;
        __syncthreads();
        if (t + 1 < tiles) av = aptr[(t + 1) * 8];
        if (t + 3 < tiles) { ISSUE_W(t + 3); } else { COMMIT_EMPTY; }

        const float* sWk = &sW[(t & 3) * 2048 + ct * 128 + 4 * lane];
        const float* sAk = &sA[(t & 1) * 256 + rq * 8];
        #pragma unroll
        for (int k = 0; k < 8; k++) {
            float4 wv = *(const float4*)(sWk + k * 256);
            ulonglong2 a01 = *(const ulonglong2*)(sAk + k * 32);
            ulonglong2 a23 = *(const ulonglong2*)(sAk + k * 32 + 4);
            ull wb0 = bcast2(wv.x), wb1 = bcast2(wv.y);
            ull wb2 = bcast2(wv.z), wb3 = bcast2(wv.w);
            ffma2(acc[0],  a01.x, wb0); ffma2(acc[1],  a01.x, wb1);
            ffma2(acc[2],  a01.x, wb2); ffma2(acc[3],  a01.x, wb3);
            ffma2(acc[4],  a01.y, wb0); ffma2(acc[5],  a01.y, wb1);
            ffma2(acc[6],  a01.y, wb2); ffma2(acc[7],  a01.y, wb3);
            ffma2(acc[8],  a23.x, wb0); ffma2(acc[9],  a23.x, wb1);
            ffma2(acc[10], a23.x, wb2); ffma2(acc[11], a23.x, wb3);
            ffma2(acc[12], a23.y, wb0); ffma2(acc[13], a23.y, wb1);
            ffma2(acc[14], a23.y, wb2); ffma2(acc[15], a23.y, wb3);
        }
        __syncthreads();
    }
    #undef ISSUE_W
    #undef COMMIT_EMPTY

    // ---- direct flush: 4 row-pairs x float4 -> red.global.add.v4 ----
    const int cg = c0 + ct * 128 + 4 * lane;
    #pragma unroll
    for (int p = 0; p < 4; p++) {
        const int row = rq * 8 + 2 * p;
        float4 vlo, vhi;
        unpack2(acc[p * 4 + 0], vlo.x, vhi.x);
        unpack2(acc[p * 4 + 1], vlo.y, vhi.y);
        unpack2(acc[p * 4 + 2], vlo.z, vhi.z);
        unpack2(acc[p * 4 + 3], vlo.w, vhi.w);
        #pragma unroll
        for (int h = 0; h < 2; h++) {
            const int r = row + h;
            float4 f = h ? vhi : vlo;
            float* p_;
            if constexpr (MODE == 0)
                p_ = (gt == 0) ? &g_f0[r * D + cg]
                               : &g_Ap[((size_t)r * T + gt - 1) * D + cg];
            else if constexpr (MODE == 1)
                p_ = (gt == 0) ? &g_z[r * H + cg]
                               : &g_Z1[((size_t)r * T + gt - 1) * H + cg];
            else if constexpr (MODE == 2)
                p_ = (gt == 0) ? &g_base[r * D + cg]
                               : &g_F2[((size_t)r * T + gt - 1) * D + cg];
            else if constexpr (MODE == 3)
                p_ = &g_dzp[r * H + cg];
            else
                p_ = &dst[r * D + cg];
            red4(p_, f);
        }
    }
}

// ---------------- K5: metanet -------------------------------------------------
__global__ void meta_kernel(const float* __restrict__ mW1, const float* __restrict__ mb1,
                            const float* __restrict__ mW2, const float* __restrict__ mb2)
{
    __shared__ float sb[D];
    __shared__ float sg[MH];
    const int b = blockIdx.x;
    const int tid = threadIdx.x;   // 192
    for (int i = tid; i < D; i += MH) sb[i] = g_base[b * D + i];
    __syncthreads();
    float h = mb1[tid];
    #pragma unroll 8
    for (int k = 0; k < D; k++) h = fmaf(sb[k], mW1[k * MH + tid], h);
    sg[tid] = fmaxf(h, 0.f);
    __syncthreads();
    if (tid < T * 6) {
        float cc = mb2[tid];
        #pragma unroll 8
        for (int k = 0; k < MH; k++) cc = fmaf(sg[k], mW2[k * (T * 6) + tid], cc);
        g_coef[b * (T * 6) + tid] = cc;
    }
}

// ---------------- K6: coefficient contraction + output init ------------------
__global__ void combine_kernel(const float* __restrict__ dbp,
                               const float* __restrict__ db1,
                               const float* __restrict__ db2,
                               float* __restrict__ dst)
{
    __shared__ float sc[T * 6];
    const int b = blockIdx.x;
    const int tid = threadIdx.x;
    if (tid < T * 6) sc[tid] = g_coef[b * (T * 6) + tid];
    __syncthreads();
    const int n = blockIdx.y * 256 + tid;
    if (n < D) {
        float s = 0.f;
        #pragma unroll
        for (int t = 0; t < T; t++)
            s += sc[t * 6 + 0] * g_Ap[((size_t)b * T + t) * D + n]
               + sc[t * 6 + 1] * dbp[t * D + n];
        g_df0[b * D + n] = s;
    } else if (n < D + H) {
        const int j = n - D;
        float s = 0.f;
        #pragma unroll
        for (int t = 0; t < T; t++)
            s += sc[t * 6 + 2] * g_Z1[((size_t)b * T + t) * H + j]
               + sc[t * 6 + 3] * db1[t * H + j];
        g_dzp[b * H + j] = s;
    } else {
        const int j = n - D - H;
        float s = g_base[b * D + j];
        #pragma unroll
        for (int t = 0; t < T; t++)
            s += sc[t * 6 + 4] * g_F2[((size_t)b * T + t) * D + j]
               + sc[t * 6 + 5] * db2[t * D + j];
        dst[b * D + j] = s;
    }
}

// ---------------- launch ------------------------------------------------------
extern "C" void kernel_launch(void* const* d_in, const int* in_sizes, int n_in,
                              void* d_out, int out_size)
{
    const float* x   = (const float*)d_in[0];
    const float* Wp  = (const float*)d_in[1];
    const float* bp  = (const float*)d_in[2];
    const float* W1  = (const float*)d_in[3];
    const float* b1  = (const float*)d_in[4];
    const float* W2  = (const float*)d_in[5];
    const float* b2  = (const float*)d_in[6];
    const float* dWp = (const float*)d_in[7];
    const float* dbp = (const float*)d_in[8];
    const float* dW1 = (const float*)d_in[9];
    const float* db1 = (const float*)d_in[10];
    const float* dW2 = (const float*)d_in[11];
    const float* db2 = (const float*)d_in[12];
    const float* mW1 = (const float*)d_in[13];
    const float* mb1 = (const float*)d_in[14];
    const float* mW2 = (const float*)d_in[15];
    const float* mb2 = (const float*)d_in[16];
    float* out = (float*)d_out;

    patch_mean_kernel<<<96, 256>>>(x);
    init_kernel<<<384, 256>>>(bp, b1, b2);
    // K2: f0/Ap   N=6912/256=27 nblk, Y=16 (KC=48,  6 tiles)  432 blocks
    gemm5<768, 768, 0><<<dim3(27, 16), 256>>>(Wp, dWp, nullptr);
    // K3: z/Z1    N=27648/256=108,   Y=4  (KC=192, 24 tiles) 432 blocks
    gemm5<768, 3072, 1><<<dim3(108, 4), 256>>>(W1, dW1, nullptr);
    relu_kernel<<<384, 256>>>();
    // K4: base/F2 N=6912/256=27,     Y=16 (KC=192, 24 tiles) 432 blocks
    gemm5<3072, 768, 2><<<dim3(27, 16), 256>>>(W2, dW2, nullptr);
    meta_kernel<<<B, MH>>>(mW1, mb1, mW2, mb2);
    combine_kernel<<<dim3(B, 18), 256>>>(dbp, db1, db2, out);
    // K7: dzp += df0@W1  N=3072/256=12, Y=24 (KC=32, 4 tiles) 288 blocks
    gemm5<768, 3072, 3><<<dim3(12, 24), 256>>>(W1, nullptr, nullptr);
    mask_kernel<<<384, 256>>>();
    // K8: out += df@W2   N=768/256=3,   Y=96 (KC=32, 4 tiles) 288 blocks
    gemm5<3072, 768, 4><<<dim3(3, 96), 256>>>(W2, nullptr, out);
}

// round 6
// speedup vs baseline: 1.2753x; 1.0048x over previous
#include <cuda_runtime.h>
#include <cstdint>

#define B  32
#define D  768
#define H  3072
#define T  8
#define MH 192

typedef unsigned long long ull;

// ---------------- scratch (device globals) ----------------------------------
__device__ float g_m  [B*D];
__device__ float g_f0 [B*D];
__device__ float g_Ap [B*T*D];
__device__ float g_z  [B*H];
__device__ float g_f  [B*H];
__device__ float g_Z1 [B*T*H];
__device__ float g_base[B*D];
__device__ float g_F2 [B*T*D];
__device__ float g_coef[B*T*6];
__device__ float g_df0[B*D];
__device__ float g_dzp[B*H];
__device__ float g_df [B*H];

// ---------------- packed f32x2 helpers --------------------------------------
__device__ __forceinline__ void ffma2(ull &d, ull a, ull b) {
    asm("fma.rn.f32x2 %0, %1, %2, %0;" : "+l"(d) : "l"(a), "l"(b));
}
__device__ __forceinline__ ull bcast2(float w) {
    ull r; asm("mov.b64 %0, {%1, %1};" : "=l"(r) : "f"(w)); return r;
}
__device__ __forceinline__ void unpack2(ull v, float &lo, float &hi) {
    asm("mov.b64 {%0, %1}, %2;" : "=f"(lo), "=f"(hi) : "l"(v));
}
__device__ __forceinline__ ull addp(ull a, ull b) {
    ull r; asm("add.rn.f32x2 %0, %1, %2;" : "=l"(r) : "l"(a), "l"(b)); return r;
}
__device__ __forceinline__ void red4(float* p, float4 f) {
    asm volatile("red.global.add.v4.f32 [%0], {%1,%2,%3,%4};"
                 :: "l"(p), "f"(f.x), "f"(f.y), "f"(f.z), "f"(f.w) : "memory");
}
__device__ __forceinline__ void cpasync16(unsigned dstp, const float* src) {
    asm volatile("cp.async.ca.shared.global [%0], [%1], 16;" :: "r"(dstp), "l"(src));
}

// ---------------- K1: patch mean ---------------------------------------------
__global__ void patch_mean_kernel(const float* __restrict__ x) {
    int bc = blockIdx.x;            // 0..95
    int b = bc / 3, c = bc % 3;
    int tid = threadIdx.x;          // 256
    int dy = tid >> 4, dx = tid & 15;
    const float* base = x + (((size_t)b * 3 + c) * 224 + dy) * 224 + dx;
    float s = 0.f;
    #pragma unroll
    for (int py = 0; py < 14; py++) {
        const float* r = base + py * 16 * 224;
        #pragma unroll
        for (int px = 0; px < 14; px++) s += r[px * 16];
    }
    g_m[b * D + c * 256 + dy * 16 + dx] = s * (1.0f / 196.0f);
}

// ---------------- init: bias preload + zeros ---------------------------------
__global__ void init_kernel(const float* __restrict__ bp,
                            const float* __restrict__ b1,
                            const float* __restrict__ b2) {
    int i = blockIdx.x * 256 + threadIdx.x;
    if (i < B * D) { g_f0[i] = bp[i % D]; g_base[i] = b2[i % D]; }
    if (i < B * H) g_z[i] = b1[i % H];
    for (int j = i; j < B * T * D; j += gridDim.x * 256) { g_Ap[j] = 0.f; g_F2[j] = 0.f; }
    for (int j = i; j < B * T * H; j += gridDim.x * 256) g_Z1[j] = 0.f;
}

__global__ void relu_kernel() {
    int i = blockIdx.x * 256 + threadIdx.x;
    if (i < B * H) g_f[i] = fmaxf(g_z[i], 0.f);
}
__global__ void mask_kernel() {
    int i = blockIdx.x * 256 + threadIdx.x;
    if (i < B * H) g_df[i] = (g_z[i] > 0.f) ? g_dzp[i] : 0.f;
}

// ---------------- skinny GEMM v6 ---------------------------------------------
// Tile 256 cols x 32 rows. 8 warps = 2 col-tiles (ct) x 2 row-halves (rh, 16
// rows) x 2 k-parities (kh: odd/even k of the shared 8k tile).
// Lane: 4 consecutive cols, 8 row-pairs packed f32x2 over ROWS (32 accs).
// Per warp-k: 1 W LDS.128 + 4 A broadcast LDS.128 + 4 bcast + 32 ffma2.
// kh pair merged via one smem round; single red.global.add.v4 flush.
// MODE: 0:g_f0/g_Ap  1:g_z/g_Z1  2:g_base/g_F2  3:g_dzp(A=g_df0)  4:dst(A=g_df)
template<int KTOT, int NC, int MODE>
__global__ void __launch_bounds__(256, 2) gemm6(
    const float* __restrict__ W0,
    const float* __restrict__ Wd,
    float* __restrict__ dst)
{
    __shared__ __align__(16) float sW[4 * 2048];   // 32KB: 4 stages of 8k x 256
    __shared__ __align__(16) float sA[2 * 256];    // 2KB: 2 buffers of 8k x 32

    const int tid  = threadIdx.x;
    const int w    = tid >> 5;
    const int lane = tid & 31;
    const int ct   = w & 1;          // col tile (128 cols)
    const int rh   = (w >> 1) & 1;   // row half (16 rows)
    const int kh   = w >> 2;         // k parity

    const float* A;
    if      (MODE == 0) A = g_m;
    else if (MODE == 1) A = g_f0;
    else if (MODE == 2) A = g_f;
    else if (MODE == 3) A = g_df0;
    else                A = g_df;

    const int n0 = blockIdx.x * 256;
    const int gt = n0 / NC;
    const int c0 = n0 % NC;
    const float* wbase = (gt == 0 ? W0 : Wd + (size_t)(gt - 1) * KTOT * NC) + c0;

    const int KC    = KTOT / gridDim.y;
    const int kbeg  = blockIdx.y * KC;
    const int tiles = KC >> 3;                     // 8 k per tile

    ull acc[32];                                   // [pair*4 + col]
    #pragma unroll
    for (int i = 0; i < 32; i++) acc[i] = 0ULL;

    #define ISSUE_W(t)                                                          \
    {                                                                           \
        const int st_ = (t) & 3;                                                \
        _Pragma("unroll")                                                       \
        for (int i_ = 0; i_ < 2; i_++) {                                        \
            int idx_ = i_ * 256 + tid;                                          \
            int row_ = idx_ >> 6, seg_ = idx_ & 63;                             \
            const float* src_ = wbase + (size_t)(kbeg + (t) * 8 + row_) * NC + seg_ * 4; \
            unsigned dp_ = (unsigned)__cvta_generic_to_shared(                  \
                               &sW[st_ * 2048 + row_ * 256 + seg_ * 4]);        \
            cpasync16(dp_, src_);                                               \
        }                                                                       \
        asm volatile("cp.async.commit_group;");                                 \
    }
    #define COMMIT_EMPTY asm volatile("cp.async.commit_group;")

    // A prefetch: thread stages element (k = tid>>5, row = tid&31)
    const int arow = tid & 31, akk = tid >> 5;
    const float* aptr = A + (size_t)arow * KTOT + kbeg + akk;
    float av = *aptr;

    ISSUE_W(0);
    if (tiles > 1) { ISSUE_W(1); } else { COMMIT_EMPTY; }
    if (tiles > 2) { ISSUE_W(2); } else { COMMIT_EMPTY; }

    for (int t = 0; t < tiles; t++) {
        asm volatile("cp.async.wait_group 2;");
        sA[(t & 1) * 256 + akk * 32 + arow] = av;
        __syncthreads();
        if (t + 1 < tiles) av = aptr[(t + 1) * 8];
        if (t + 3 < tiles) { ISSUE_W(t + 3); } else { COMMIT_EMPTY; }

        const float* sWk = &sW[(t & 3) * 2048 + ct * 128 + 4 * lane];
        const float* sAk = &sA[(t & 1) * 256 + rh * 16];
        #pragma unroll
        for (int kk = 0; kk < 4; kk++) {
            const int k = 2 * kk + kh;
            float4 wv = *(const float4*)(sWk + k * 256);
            const ulonglong2* ap = (const ulonglong2*)(sAk + k * 32);
            ulonglong2 a0 = ap[0], a1 = ap[1], a2 = ap[2], a3 = ap[3];
            ull wb0 = bcast2(wv.x), wb1 = bcast2(wv.y);
            ull wb2 = bcast2(wv.z), wb3 = bcast2(wv.w);
            ffma2(acc[0],  a0.x, wb0); ffma2(acc[1],  a0.x, wb1);
            ffma2(acc[2],  a0.x, wb2); ffma2(acc[3],  a0.x, wb3);
            ffma2(acc[4],  a0.y, wb0); ffma2(acc[5],  a0.y, wb1);
            ffma2(acc[6],  a0.y, wb2); ffma2(acc[7],  a0.y, wb3);
            ffma2(acc[8],  a1.x, wb0); ffma2(acc[9],  a1.x, wb1);
            ffma2(acc[10], a1.x, wb2); ffma2(acc[11], a1.x, wb3);
            ffma2(acc[12], a1.y, wb0); ffma2(acc[13], a1.y, wb1);
            ffma2(acc[14], a1.y, wb2); ffma2(acc[15], a1.y, wb3);
            ffma2(acc[16], a2.x, wb0); ffma2(acc[17], a2.x, wb1);
            ffma2(acc[18], a2.x, wb2); ffma2(acc[19], a2.x, wb3);
            ffma2(acc[20], a2.y, wb0); ffma2(acc[21], a2.y, wb1);
            ffma2(acc[22], a2.y, wb2); ffma2(acc[23], a2.y, wb3);
            ffma2(acc[24], a3.x, wb0); ffma2(acc[25], a3.x, wb1);
            ffma2(acc[26], a3.x, wb2); ffma2(acc[27], a3.x, wb3);
            ffma2(acc[28], a3.y, wb0); ffma2(acc[29], a3.y, wb1);
            ffma2(acc[30], a3.y, wb2); ffma2(acc[31], a3.y, wb3);
        }
        __syncthreads();
    }
    #undef ISSUE_W
    #undef COMMIT_EMPTY

    // ---- merge kh pair via one smem round, flush once ----
    ull* sred = (ull*)sW;                 // 32KB = 4096 ull
    const int role = w & 3;               // (ct, rh)
    if (kh == 1) {
        #pragma unroll
        for (int i = 0; i < 32; i++) sred[role * 1024 + i * 32 + lane] = acc[i];
    }
    __syncthreads();
    if (kh == 0) {
        #pragma unroll
        for (int i = 0; i < 32; i++)
            acc[i] = addp(acc[i], sred[role * 1024 + i * 32 + lane]);

        const int cg = c0 + ct * 128 + 4 * lane;
        #pragma unroll
        for (int p = 0; p < 8; p++) {
            const int row = rh * 16 + 2 * p;
            float4 vlo, vhi;
            unpack2(acc[p * 4 + 0], vlo.x, vhi.x);
            unpack2(acc[p * 4 + 1], vlo.y, vhi.y);
            unpack2(acc[p * 4 + 2], vlo.z, vhi.z);
            unpack2(acc[p * 4 + 3], vlo.w, vhi.w);
            #pragma unroll
            for (int h = 0; h < 2; h++) {
                const int r = row + h;
                float4 f = h ? vhi : vlo;
                float* p_;
                if constexpr (MODE == 0)
                    p_ = (gt == 0) ? &g_f0[r * D + cg]
                                   : &g_Ap[((size_t)r * T + gt - 1) * D + cg];
                else if constexpr (MODE == 1)
                    p_ = (gt == 0) ? &g_z[r * H + cg]
                                   : &g_Z1[((size_t)r * T + gt - 1) * H + cg];
                else if constexpr (MODE == 2)
                    p_ = (gt == 0) ? &g_base[r * D + cg]
                                   : &g_F2[((size_t)r * T + gt - 1) * D + cg];
                else if constexpr (MODE == 3)
                    p_ = &g_dzp[r * H + cg];
                else
                    p_ = &dst[r * D + cg];
                red4(p_, f);
            }
        }
    }
}

// ---------------- K5: metanet -------------------------------------------------
__global__ void meta_kernel(const float* __restrict__ mW1, const float* __restrict__ mb1,
                            const float* __restrict__ mW2, const float* __restrict__ mb2)
{
    __shared__ float sb[D];
    __shared__ float sg[MH];
    const int b = blockIdx.x;
    const int tid = threadIdx.x;   // 192
    for (int i = tid; i < D; i += MH) sb[i] = g_base[b * D + i];
    __syncthreads();
    float h = mb1[tid];
    #pragma unroll 8
    for (int k = 0; k < D; k++) h = fmaf(sb[k], mW1[k * MH + tid], h);
    sg[tid] = fmaxf(h, 0.f);
    __syncthreads();
    if (tid < T * 6) {
        float cc = mb2[tid];
        #pragma unroll 8
        for (int k = 0; k < MH; k++) cc = fmaf(sg[k], mW2[k * (T * 6) + tid], cc);
        g_coef[b * (T * 6) + tid] = cc;
    }
}

// ---------------- K6: coefficient contraction + output init ------------------
__global__ void combine_kernel(const float* __restrict__ dbp,
                               const float* __restrict__ db1,
                               const float* __restrict__ db2,
                               float* __restrict__ dst)
{
    __shared__ float sc[T * 6];
    const int b = blockIdx.x;
    const int tid = threadIdx.x;
    if (tid < T * 6) sc[tid] = g_coef[b * (T * 6) + tid];
    __syncthreads();
    const int n = blockIdx.y * 256 + tid;
    if (n < D) {
        float s = 0.f;
        #pragma unroll
        for (int t = 0; t < T; t++)
            s += sc[t * 6 + 0] * g_Ap[((size_t)b * T + t) * D + n]
               + sc[t * 6 + 1] * dbp[t * D + n];
        g_df0[b * D + n] = s;
    } else if (n < D + H) {
        const int j = n - D;
        float s = 0.f;
        #pragma unroll
        for (int t = 0; t < T; t++)
            s += sc[t * 6 + 2] * g_Z1[((size_t)b * T + t) * H + j]
               + sc[t * 6 + 3] * db1[t * H + j];
        g_dzp[b * H + j] = s;
    } else {
        const int j = n - D - H;
        float s = g_base[b * D + j];
        #pragma unroll
        for (int t = 0; t < T; t++)
            s += sc[t * 6 + 4] * g_F2[((size_t)b * T + t) * D + j]
               + sc[t * 6 + 5] * db2[t * D + j];
        dst[b * D + j] = s;
    }
}

// ---------------- launch ------------------------------------------------------
extern "C" void kernel_launch(void* const* d_in, const int* in_sizes, int n_in,
                              void* d_out, int out_size)
{
    const float* x   = (const float*)d_in[0];
    const float* Wp  = (const float*)d_in[1];
    const float* bp  = (const float*)d_in[2];
    const float* W1  = (const float*)d_in[3];
    const float* b1  = (const float*)d_in[4];
    const float* W2  = (const float*)d_in[5];
    const float* b2  = (const float*)d_in[6];
    const float* dWp = (const float*)d_in[7];
    const float* dbp = (const float*)d_in[8];
    const float* dW1 = (const float*)d_in[9];
    const float* db1 = (const float*)d_in[10];
    const float* dW2 = (const float*)d_in[11];
    const float* db2 = (const float*)d_in[12];
    const float* mW1 = (const float*)d_in[13];
    const float* mb1 = (const float*)d_in[14];
    const float* mW2 = (const float*)d_in[15];
    const float* mb2 = (const float*)d_in[16];
    float* out = (float*)d_out;

    patch_mean_kernel<<<96, 256>>>(x);
    init_kernel<<<384, 256>>>(bp, b1, b2);
    // K2: f0/Ap   nblk=27, Y=16 (KC=48,  6 tiles)  432 blocks (~1.46 waves)
    gemm6<768, 768, 0><<<dim3(27, 16), 256>>>(Wp, dWp, nullptr);
    // K3: z/Z1    nblk=108, Y=8 (KC=96, 12 tiles)  864 blocks (~2.92 waves)
    gemm6<768, 3072, 1><<<dim3(108, 8), 256>>>(W1, dW1, nullptr);
    relu_kernel<<<384, 256>>>();
    // K4: base/F2 nblk=27, Y=32 (KC=96, 12 tiles)  864 blocks (~2.92 waves)
    gemm6<3072, 768, 2><<<dim3(27, 32), 256>>>(W2, dW2, nullptr);
    meta_kernel<<<B, MH>>>(mW1, mb1, mW2, mb2);
    combine_kernel<<<dim3(B, 18), 256>>>(dbp, db1, db2, out);
    // K7: dzp += df0@W1  nblk=12, Y=24 (KC=32, 4 tiles) 288 blocks
    gemm6<768, 3072, 3><<<dim3(12, 24), 256>>>(W1, nullptr, nullptr);
    mask_kernel<<<384, 256>>>();
    // K8: out += df@W2   nblk=3, Y=96 (KC=32, 4 tiles) 288 blocks
    gemm6<3072, 768, 4><<<dim3(3, 96), 256>>>(W2, nullptr, out);
}

// round 7
// speedup vs baseline: 1.2779x; 1.0021x over previous
#include <cuda_runtime.h>
#include <cstdint>

#define B  32
#define D  768
#define H  3072
#define T  8
#define MH 192

typedef unsigned long long ull;

// ---------------- scratch (device globals) ----------------------------------
__device__ float g_m  [B*D];
__device__ float g_f0 [B*D];
__device__ float g_Ap [B*T*D];
__device__ float g_z  [B*H];
__device__ float g_f  [B*H];
__device__ float g_Z1 [B*T*H];
__device__ float g_base[B*D];
__device__ float g_F2 [B*T*D];
__device__ float g_coef[B*T*6];
__device__ float g_df0[B*D];
__device__ float g_dzp[B*H];
__device__ float g_df [B*H];

// ---------------- packed f32x2 helpers --------------------------------------
__device__ __forceinline__ void ffma2(ull &d, ull a, ull b) {
    asm("fma.rn.f32x2 %0, %1, %2, %0;" : "+l"(d) : "l"(a), "l"(b));
}
__device__ __forceinline__ ull bcast2(float w) {
    ull r; asm("mov.b64 %0, {%1, %1};" : "=l"(r) : "f"(w)); return r;
}
__device__ __forceinline__ void unpack2(ull v, float &lo, float &hi) {
    asm("mov.b64 {%0, %1}, %2;" : "=f"(lo), "=f"(hi) : "l"(v));
}
__device__ __forceinline__ ull addp(ull a, ull b) {
    ull r; asm("add.rn.f32x2 %0, %1, %2;" : "=l"(r) : "l"(a), "l"(b)); return r;
}
__device__ __forceinline__ void red4(float* p, float4 f) {
    asm volatile("red.global.add.v4.f32 [%0], {%1,%2,%3,%4};"
                 :: "l"(p), "f"(f.x), "f"(f.y), "f"(f.z), "f"(f.w) : "memory");
}
// ---------------- bulk-DMA helpers ------------------------------------------
__device__ __forceinline__ void mbar_init(unsigned mbar, unsigned cnt) {
    asm volatile("mbarrier.init.shared.b64 [%0], %1;" :: "r"(mbar), "r"(cnt) : "memory");
}
__device__ __forceinline__ void mbar_wait(unsigned mbar, unsigned parity) {
    asm volatile(
        "{\n\t.reg .pred P;\n"
        "W_%=:\n\t"
        "mbarrier.try_wait.parity.acquire.cta.shared::cta.b64 P, [%0], %1;\n\t"
        "@P bra D_%=;\n\t"
        "bra W_%=;\n"
        "D_%=:\n\t}"
        :: "r"(mbar), "r"(parity) : "memory");
}
template<int NC>
__device__ __forceinline__ void issue_tile(const float* wrow0, int t,
                                           unsigned swb, unsigned mbar) {
    asm volatile("mbarrier.arrive.expect_tx.shared.b64 _, [%0], %1;"
                 :: "r"(mbar), "r"(8192u) : "memory");
    const float* src = wrow0 + (size_t)t * 8 * NC;
    unsigned dst = swb + (unsigned)(t & 3) * 8192u;
    #pragma unroll
    for (int r = 0; r < 8; r++) {
        asm volatile(
            "cp.async.bulk.shared::cta.global.mbarrier::complete_tx::bytes "
            "[%0], [%1], 1024, [%2];"
            :: "r"(dst + r * 1024u), "l"(src + (size_t)r * NC), "r"(mbar)
            : "memory");
    }
}

// ---------------- K1: patch mean ---------------------------------------------
__global__ void patch_mean_kernel(const float* __restrict__ x) {
    int bc = blockIdx.x;            // 0..95
    int b = bc / 3, c = bc % 3;
    int tid = threadIdx.x;          // 256
    int dy = tid >> 4, dx = tid & 15;
    const float* base = x + (((size_t)b * 3 + c) * 224 + dy) * 224 + dx;
    float s = 0.f;
    #pragma unroll
    for (int py = 0; py < 14; py++) {
        const float* r = base + py * 16 * 224;
        #pragma unroll
        for (int px = 0; px < 14; px++) s += r[px * 16];
    }
    g_m[b * D + c * 256 + dy * 16 + dx] = s * (1.0f / 196.0f);
}

// ---------------- init: bias preload + zeros ---------------------------------
__global__ void init_kernel(const float* __restrict__ bp,
                            const float* __restrict__ b1,
                            const float* __restrict__ b2) {
    int i = blockIdx.x * 256 + threadIdx.x;
    if (i < B * D) { g_f0[i] = bp[i % D]; g_base[i] = b2[i % D]; }
    if (i < B * H) g_z[i] = b1[i % H];
    for (int j = i; j < B * T * D; j += gridDim.x * 256) { g_Ap[j] = 0.f; g_F2[j] = 0.f; }
    for (int j = i; j < B * T * H; j += gridDim.x * 256) g_Z1[j] = 0.f;
}

__global__ void relu_kernel() {
    int i = blockIdx.x * 256 + threadIdx.x;
    if (i < B * H) g_f[i] = fmaxf(g_z[i], 0.f);
}
__global__ void mask_kernel() {
    int i = blockIdx.x * 256 + threadIdx.x;
    if (i < B * H) g_df[i] = (g_z[i] > 0.f) ? g_dzp[i] : 0.f;
}

// ---------------- skinny GEMM v7: bulk-DMA weight stream ----------------------
// Same compute core as v6 (256 cols x 32 rows; warps = 2ct x 2rh x 2kh; lane =
// 4 cols x 8 row-pairs packed over rows). W streamed via cp.async.bulk:
// 8 x 1KB UBLKCP per 8k tile from one elected thread, mbarrier completion.
// MODE: 0:g_f0/g_Ap  1:g_z/g_Z1  2:g_base/g_F2  3:g_dzp(A=g_df0)  4:dst(A=g_df)
template<int KTOT, int NC, int MODE>
__global__ void __launch_bounds__(256, 2) gemm7(
    const float* __restrict__ W0,
    const float* __restrict__ Wd,
    float* __restrict__ dst)
{
    __shared__ __align__(128) float sW[4 * 2048];   // 32KB: 4 stages of 8k x 256
    __shared__ __align__(16)  float sA[2 * 256];    // 2KB
    __shared__ __align__(8)   ull   smb[4];         // mbarriers

    const int tid  = threadIdx.x;
    const int w    = tid >> 5;
    const int lane = tid & 31;
    const int ct   = w & 1;
    const int rh   = (w >> 1) & 1;
    const int kh   = w >> 2;

    const unsigned swb = (unsigned)__cvta_generic_to_shared(sW);
    const unsigned mb0 = (unsigned)__cvta_generic_to_shared(smb);

    const float* A;
    if      (MODE == 0) A = g_m;
    else if (MODE == 1) A = g_f0;
    else if (MODE == 2) A = g_f;
    else if (MODE == 3) A = g_df0;
    else                A = g_df;

    const int n0 = blockIdx.x * 256;
    const int gt = n0 / NC;
    const int c0 = n0 % NC;
    const float* wbase = (gt == 0 ? W0 : Wd + (size_t)(gt - 1) * KTOT * NC) + c0;

    const int KC    = KTOT / gridDim.y;
    const int kbeg  = blockIdx.y * KC;
    const int tiles = KC >> 3;
    const float* wrow0 = wbase + (size_t)kbeg * NC;

    if (tid == 0) {
        #pragma unroll
        for (int i = 0; i < 4; i++) mbar_init(mb0 + i * 8, 1);
        asm volatile("fence.proxy.async.shared::cta;" ::: "memory");
    }
    __syncthreads();

    if (tid == 0) {
        issue_tile<NC>(wrow0, 0, swb, mb0);
        if (tiles > 1) issue_tile<NC>(wrow0, 1, swb, mb0 + 8);
        if (tiles > 2) issue_tile<NC>(wrow0, 2, swb, mb0 + 16);
    }

    ull acc[32];
    #pragma unroll
    for (int i = 0; i < 32; i++) acc[i] = 0ULL;

    // A prefetch: thread stages element (k = tid>>5, row = tid&31)
    const int arow = tid & 31, akk = tid >> 5;
    const float* aptr = A + (size_t)arow * KTOT + kbeg + akk;
    float av = *aptr;

    for (int t = 0; t < tiles; t++) {
        mbar_wait(mb0 + (t & 3) * 8, (t >> 2) & 1);
        sA[(t & 1) * 256 + akk * 32 + arow] = av;
        __syncthreads();
        if (t + 1 < tiles) av = aptr[(t + 1) * 8];
        if (tid == 0 && t + 3 < tiles)
            issue_tile<NC>(wrow0, t + 3, swb, mb0 + ((t + 3) & 3) * 8);

        const float* sWk = &sW[(t & 3) * 2048 + ct * 128 + 4 * lane];
        const float* sAk = &sA[(t & 1) * 256 + rh * 16];
        #pragma unroll
        for (int kk = 0; kk < 4; kk++) {
            const int k = 2 * kk + kh;
            float4 wv = *(const float4*)(sWk + k * 256);
            const ulonglong2* ap = (const ulonglong2*)(sAk + k * 32);
            ulonglong2 a0 = ap[0], a1 = ap[1], a2 = ap[2], a3 = ap[3];
            ull wb0 = bcast2(wv.x), wb1 = bcast2(wv.y);
            ull wb2 = bcast2(wv.z), wb3 = bcast2(wv.w);
            ffma2(acc[0],  a0.x, wb0); ffma2(acc[1],  a0.x, wb1);
            ffma2(acc[2],  a0.x, wb2); ffma2(acc[3],  a0.x, wb3);
            ffma2(acc[4],  a0.y, wb0); ffma2(acc[5],  a0.y, wb1);
            ffma2(acc[6],  a0.y, wb2); ffma2(acc[7],  a0.y, wb3);
            ffma2(acc[8],  a1.x, wb0); ffma2(acc[9],  a1.x, wb1);
            ffma2(acc[10], a1.x, wb2); ffma2(acc[11], a1.x, wb3);
            ffma2(acc[12], a1.y, wb0); ffma2(acc[13], a1.y, wb1);
            ffma2(acc[14], a1.y, wb2); ffma2(acc[15], a1.y, wb3);
            ffma2(acc[16], a2.x, wb0); ffma2(acc[17], a2.x, wb1);
            ffma2(acc[18], a2.x, wb2); ffma2(acc[19], a2.x, wb3);
            ffma2(acc[20], a2.y, wb0); ffma2(acc[21], a2.y, wb1);
            ffma2(acc[22], a2.y, wb2); ffma2(acc[23], a2.y, wb3);
            ffma2(acc[24], a3.x, wb0); ffma2(acc[25], a3.x, wb1);
            ffma2(acc[26], a3.x, wb2); ffma2(acc[27], a3.x, wb3);
            ffma2(acc[28], a3.y, wb0); ffma2(acc[29], a3.y, wb1);
            ffma2(acc[30], a3.y, wb2); ffma2(acc[31], a3.y, wb3);
        }
        __syncthreads();
    }

    // ---- merge kh pair via one smem round, flush once ----
    ull* sred = (ull*)sW;
    const int role = w & 3;               // (ct, rh)
    if (kh == 1) {
        #pragma unroll
        for (int i = 0; i < 32; i++) sred[role * 1024 + i * 32 + lane] = acc[i];
    }
    __syncthreads();
    if (kh == 0) {
        #pragma unroll
        for (int i = 0; i < 32; i++)
            acc[i] = addp(acc[i], sred[role * 1024 + i * 32 + lane]);

        const int cg = c0 + ct * 128 + 4 * lane;
        #pragma unroll
        for (int p = 0; p < 8; p++) {
            const int row = rh * 16 + 2 * p;
            float4 vlo, vhi;
            unpack2(acc[p * 4 + 0], vlo.x, vhi.x);
            unpack2(acc[p * 4 + 1], vlo.y, vhi.y);
            unpack2(acc[p * 4 + 2], vlo.z, vhi.z);
            unpack2(acc[p * 4 + 3], vlo.w, vhi.w);
            #pragma unroll
            for (int h = 0; h < 2; h++) {
                const int r = row + h;
                float4 f = h ? vhi : vlo;
                float* p_;
                if constexpr (MODE == 0)
                    p_ = (gt == 0) ? &g_f0[r * D + cg]
                                   : &g_Ap[((size_t)r * T + gt - 1) * D + cg];
                else if constexpr (MODE == 1)
                    p_ = (gt == 0) ? &g_z[r * H + cg]
                                   : &g_Z1[((size_t)r * T + gt - 1) * H + cg];
                else if constexpr (MODE == 2)
                    p_ = (gt == 0) ? &g_base[r * D + cg]
                                   : &g_F2[((size_t)r * T + gt - 1) * D + cg];
                else if constexpr (MODE == 3)
                    p_ = &g_dzp[r * H + cg];
                else
                    p_ = &dst[r * D + cg];
                red4(p_, f);
            }
        }
    }
}

// ---------------- K5: metanet -------------------------------------------------
__global__ void meta_kernel(const float* __restrict__ mW1, const float* __restrict__ mb1,
                            const float* __restrict__ mW2, const float* __restrict__ mb2)
{
    __shared__ float sb[D];
    __shared__ float sg[MH];
    const int b = blockIdx.x;
    const int tid = threadIdx.x;   // 192
    for (int i = tid; i < D; i += MH) sb[i] = g_base[b * D + i];
    __syncthreads();
    float h = mb1[tid];
    #pragma unroll 8
    for (int k = 0; k < D; k++) h = fmaf(sb[k], mW1[k * MH + tid], h);
    sg[tid] = fmaxf(h, 0.f);
    __syncthreads();
    if (tid < T * 6) {
        float cc = mb2[tid];
        #pragma unroll 8
        for (int k = 0; k < MH; k++) cc = fmaf(sg[k], mW2[k * (T * 6) + tid], cc);
        g_coef[b * (T * 6) + tid] = cc;
    }
}

// ---------------- K6: coefficient contraction + output init ------------------
__global__ void combine_kernel(const float* __restrict__ dbp,
                               const float* __restrict__ db1,
                               const float* __restrict__ db2,
                               float* __restrict__ dst)
{
    __shared__ float sc[T * 6];
    const int b = blockIdx.x;
    const int tid = threadIdx.x;
    if (tid < T * 6) sc[tid] = g_coef[b * (T * 6) + tid];
    __syncthreads();
    const int n = blockIdx.y * 256 + tid;
    if (n < D) {
        float s = 0.f;
        #pragma unroll
        for (int t = 0; t < T; t++)
            s += sc[t * 6 + 0] * g_Ap[((size_t)b * T + t) * D + n]
               + sc[t * 6 + 1] * dbp[t * D + n];
        g_df0[b * D + n] = s;
    } else if (n < D + H) {
        const int j = n - D;
        float s = 0.f;
        #pragma unroll
        for (int t = 0; t < T; t++)
            s += sc[t * 6 + 2] * g_Z1[((size_t)b * T + t) * H + j]
               + sc[t * 6 + 3] * db1[t * H + j];
        g_dzp[b * H + j] = s;
    } else {
        const int j = n - D - H;
        float s = g_base[b * D + j];
        #pragma unroll
        for (int t = 0; t < T; t++)
            s += sc[t * 6 + 4] * g_F2[((size_t)b * T + t) * D + j]
               + sc[t * 6 + 5] * db2[t * D + j];
        dst[b * D + j] = s;
    }
}

// ---------------- launch ------------------------------------------------------
extern "C" void kernel_launch(void* const* d_in, const int* in_sizes, int n_in,
                              void* d_out, int out_size)
{
    const float* x   = (const float*)d_in[0];
    const float* Wp  = (const float*)d_in[1];
    const float* bp  = (const float*)d_in[2];
    const float* W1  = (const float*)d_in[3];
    const float* b1  = (const float*)d_in[4];
    const float* W2  = (const float*)d_in[5];
    const float* b2  = (const float*)d_in[6];
    const float* dWp = (const float*)d_in[7];
    const float* dbp = (const float*)d_in[8];
    const float* dW1 = (const float*)d_in[9];
    const float* db1 = (const float*)d_in[10];
    const float* dW2 = (const float*)d_in[11];
    const float* db2 = (const float*)d_in[12];
    const float* mW1 = (const float*)d_in[13];
    const float* mb1 = (const float*)d_in[14];
    const float* mW2 = (const float*)d_in[15];
    const float* mb2 = (const float*)d_in[16];
    float* out = (float*)d_out;

    patch_mean_kernel<<<96, 256>>>(x);
    init_kernel<<<384, 256>>>(bp, b1, b2);
    // K2: f0/Ap   nblk=27, Y=16 (KC=48,  6 tiles)  432 blocks
    gemm7<768, 768, 0><<<dim3(27, 16), 256>>>(Wp, dWp, nullptr);
    // K3: z/Z1    nblk=108, Y=8 (KC=96, 12 tiles)  864 blocks
    gemm7<768, 3072, 1><<<dim3(108, 8), 256>>>(W1, dW1, nullptr);
    relu_kernel<<<384, 256>>>();
    // K4: base/F2 nblk=27, Y=32 (KC=96, 12 tiles)  864 blocks
    gemm7<3072, 768, 2><<<dim3(27, 32), 256>>>(W2, dW2, nullptr);
    meta_kernel<<<B, MH>>>(mW1, mb1, mW2, mb2);
    combine_kernel<<<dim3(B, 18), 256>>>(dbp, db1, db2, out);
    // K7: dzp += df0@W1  nblk=12, Y=24 (KC=32, 4 tiles) 288 blocks
    gemm7<768, 3072, 3><<<dim3(12, 24), 256>>>(W1, nullptr, nullptr);
    mask_kernel<<<384, 256>>>();
    // K8: out += df@W2   nblk=3, Y=96 (KC=32, 4 tiles) 288 blocks
    gemm7<3072, 768, 4><<<dim3(3, 96), 256>>>(W2, nullptr, out);
}